// round 11
// baseline (speedup 1.0000x reference)
#include <cuda_runtime.h>
#include <math.h>

#define KMIX 32
#define DDIM 32
#define MSTRIDE 576   // padded-triangular floats per mixture: sum_i 4*((i>>2)+1)

__device__ float g_M[KMIX * MSTRIDE];  // packed lower-triangular L^{-1}, rows padded to mult of 4
__device__ float g_t[KMIX * DDIM];     // t_k = M_k * mu_k
__device__ float g_c[KMIX];            // c_k = -log(phi) + 0.5*(D*log(2pi) + logdet)

__host__ __device__ constexpr int rowoff(int i) {
    int g = i >> 2, r = i & 3;
    return 8 * g * (g + 1) + r * 4 * (g + 1);
}

// ---------------- precompute: one warp per mixture ----------------
__global__ void gmm_precompute(const float* __restrict__ sigmas,
                               const float* __restrict__ mus,
                               const float* __restrict__ phis) {
    __shared__ float L[DDIM][DDIM];
    __shared__ float Mi[DDIM][DDIM];
    int k = blockIdx.x;
    int lane = threadIdx.x;

    for (int idx = lane; idx < DDIM * DDIM; idx += 32) {
        L[idx >> 5][idx & 31] = sigmas[k * DDIM * DDIM + idx];
        Mi[idx >> 5][idx & 31] = 0.0f;
    }
    __syncwarp();

    for (int j = 0; j < DDIM; j++) {
        float s = 0.0f;
        if (lane >= j) {
            s = L[lane][j];
            for (int p = 0; p < j; p++) s -= L[lane][p] * L[j][p];
        }
        __syncwarp();
        if (lane == j) L[j][j] = sqrtf(s);
        __syncwarp();
        if (lane > j) L[lane][j] = s / L[j][j];
        __syncwarp();
    }

    { // Mi = L^{-1}, lane c solves column c
        int c = lane;
        for (int i = c; i < DDIM; i++) {
            float s = (i == c) ? 1.0f : 0.0f;
            for (int p = c; p < i; p++) s -= L[i][p] * Mi[p][c];
            Mi[i][c] = s / L[i][i];
        }
    }
    __syncwarp();

    for (int i = 0; i < DDIM; i++) {
        int len = 4 * ((i >> 2) + 1);
        for (int j = lane; j < len; j += 32)
            g_M[k * MSTRIDE + rowoff(i) + j] = Mi[i][j];
    }

    {
        float tv = 0.0f;
        for (int j = 0; j <= lane; j++) tv += Mi[lane][j] * mus[k * DDIM + j];
        g_t[k * DDIM + lane] = tv;
    }

    if (lane == 0) {
        float logdet = 0.0f;
        for (int j = 0; j < DDIM; j++) logdet += logf(L[j][j]);
        logdet *= 2.0f;
        const float log2pi = 1.8378770664093453f;
        g_c[k] = -logf(phis[k]) + 0.5f * ((float)DDIM * log2pi + logdet);
    }
}

// ---------------- main ----------------
__device__ __forceinline__ unsigned long long fma2(unsigned long long a,
                                                   unsigned long long b,
                                                   unsigned long long c) {
    unsigned long long d;
    asm("fma.rn.f32x2 %0, %1, %2, %3;" : "=l"(d) : "l"(a), "l"(b), "l"(c));
    return d;
}
__device__ __forceinline__ float hadd2(unsigned long long a) {
    float lo, hi;
    asm("mov.b64 {%0, %1}, %2;" : "=f"(lo), "=f"(hi) : "l"(a));
    return lo + hi;
}
__device__ __forceinline__ unsigned long long pack2(float lo, float hi) {
    unsigned long long d;
    asm("mov.b64 %0, {%1, %2};" : "=l"(d) : "f"(lo), "f"(hi));
    return d;
}
__device__ __forceinline__ void unpack2(unsigned long long a, float& lo, float& hi) {
    asm("mov.b64 {%0, %1}, %2;" : "=f"(lo), "=f"(hi) : "l"(a));
}

#define BLK 256
#define SPT 3   // samples per thread

// smem float layout:
//   M       [0, 18432)
//   t       [18432, 19456)
//   c       [19456, 19488)
//   scr2    [19488, +2*32*BLK)   ull plane, samples 0/1 packed (64KB)
//   scr1    after                float plane, sample 2 (32KB)
#define SM_T    18432
#define SM_C    19456
#define SM_SCR2 19488                    // float index (8B aligned)
#define SM_SCR1 (SM_SCR2 + 2 * KMIX * BLK)

__global__ void __launch_bounds__(BLK)
gmm_main(const float* __restrict__ X, float* __restrict__ out, int N) {
    extern __shared__ float sh[];
    float* sM = sh;
    float* sT = sh + SM_T;
    float* sC = sh + SM_C;
    unsigned long long* sScr2 = reinterpret_cast<unsigned long long*>(sh + SM_SCR2);
    float* sScr1 = sh + SM_SCR1;

    int tid = threadIdx.x;
    {   // fill smem (float4 copies)
        const float4* gm4 = reinterpret_cast<const float4*>(g_M);
        float4* sm4 = reinterpret_cast<float4*>(sM);
        for (int i = tid; i < (KMIX * MSTRIDE) / 4; i += BLK) sm4[i] = gm4[i];
        const float4* gt4 = reinterpret_cast<const float4*>(g_t);
        float4* st4 = reinterpret_cast<float4*>(sT);
        for (int i = tid; i < (KMIX * DDIM) / 4; i += BLK) st4[i] = gt4[i];
        if (tid < KMIX) sC[tid] = g_c[tid];
    }
    __syncthreads();

    int base0 = blockIdx.x * (BLK * SPT) + tid;
    int base1 = base0 + BLK;
    int base2 = base0 + 2 * BLK;
    if (base0 >= N) return;
    bool ok1 = (base1 < N);
    bool ok2 = (base2 < N);

    // load X rows as natural j-pairs (16 x b64 per sample, zero packing cost)
    unsigned long long x0[16], x1[16], x2[16];
    {
        const ulonglong2* xp = reinterpret_cast<const ulonglong2*>(X + (size_t)base0 * DDIM);
#pragma unroll
        for (int j = 0; j < 8; j++) { ulonglong2 v = xp[j]; x0[2 * j] = v.x; x0[2 * j + 1] = v.y; }
        const ulonglong2* xq = reinterpret_cast<const ulonglong2*>(X + (size_t)(ok1 ? base1 : base0) * DDIM);
#pragma unroll
        for (int j = 0; j < 8; j++) { ulonglong2 v = xq[j]; x1[2 * j] = v.x; x1[2 * j + 1] = v.y; }
        const ulonglong2* xr = reinterpret_cast<const ulonglong2*>(X + (size_t)(ok2 ? base2 : base0) * DDIM);
#pragma unroll
        for (int j = 0; j < 8; j++) { ulonglong2 v = xr[j]; x2[2 * j] = v.x; x2[2 * j + 1] = v.y; }
    }

    float vmax0 = -3.0e38f, vmax1 = -3.0e38f, vmax2 = -3.0e38f;

#pragma unroll 1
    for (int k = 0; k < KMIX; k++) {
        const float* Mk = sM + k * MSTRIDE;
        const float4* tk4 = reinterpret_cast<const float4*>(sT + k * DDIM);
        float q0 = 0.0f, q1 = 0.0f, q2 = 0.0f;
#pragma unroll
        for (int g = 0; g < 8; g++) {
            float4 t4 = tk4[g];
#pragma unroll
            for (int r = 0; r < 4; r++) {
                const int i = 4 * g + r;
                const ulonglong2* row = reinterpret_cast<const ulonglong2*>(Mk + rowoff(i));
                unsigned long long a0 = 0ull, a1 = 0ull, a2 = 0ull;
#pragma unroll
                for (int v = 0; v < (g + 1); v++) {
                    ulonglong2 m = row[v];               // 4 floats: j..j+3 (pads are 0)
                    a0 = fma2(m.x, x0[2 * v], a0);
                    a1 = fma2(m.x, x1[2 * v], a1);
                    a2 = fma2(m.x, x2[2 * v], a2);
                    a0 = fma2(m.y, x0[2 * v + 1], a0);
                    a1 = fma2(m.y, x1[2 * v + 1], a1);
                    a2 = fma2(m.y, x2[2 * v + 1], a2);
                }
                float tv = (r == 0) ? t4.x : (r == 1) ? t4.y : (r == 2) ? t4.z : t4.w;
                float y0 = hadd2(a0) - tv;
                float y1 = hadd2(a1) - tv;
                float y2 = hadd2(a2) - tv;
                q0 = fmaf(y0, y0, q0);
                q1 = fmaf(y1, y1, q1);
                q2 = fmaf(y2, y2, q2);
            }
        }
        float c = sC[k];
        float v0 = fmaf(0.5f, q0, c);
        float v1 = fmaf(0.5f, q1, c);
        float v2 = fmaf(0.5f, q2, c);
        vmax0 = fmaxf(vmax0, v0);
        vmax1 = fmaxf(vmax1, v1);
        vmax2 = fmaxf(vmax2, v2);
        sScr2[k * BLK + tid] = pack2(v0, v1);   // own slots; no sync needed
        sScr1[k * BLK + tid] = v2;
    }

    float inv0 = 1.0f / vmax0;
    float inv1 = 1.0f / vmax1;
    float inv2 = 1.0f / vmax2;
    float4* op0 = reinterpret_cast<float4*>(out + (size_t)base0 * DDIM);
    float4* op1 = reinterpret_cast<float4*>(out + (size_t)base1 * DDIM);
    float4* op2 = reinterpret_cast<float4*>(out + (size_t)base2 * DDIM);
#pragma unroll
    for (int jq = 0; jq < 8; jq++) {
        float4 o0, o1, o2;
        float lo, hi;
#pragma unroll
        for (int c = 0; c < 4; c++) {
            int kk = 4 * jq + c;
            unpack2(sScr2[kk * BLK + tid], lo, hi);
            float r0 = lo * inv0, r1 = hi * inv1;
            float r2 = sScr1[kk * BLK + tid] * inv2;
            if (c == 0)      { o0.x = r0; o1.x = r1; o2.x = r2; }
            else if (c == 1) { o0.y = r0; o1.y = r1; o2.y = r2; }
            else if (c == 2) { o0.z = r0; o1.z = r1; o2.z = r2; }
            else             { o0.w = r0; o1.w = r1; o2.w = r2; }
        }
        op0[jq] = o0;
        if (ok1) op1[jq] = o1;
        if (ok2) op2[jq] = o2;
    }
}

extern "C" void kernel_launch(void* const* d_in, const int* in_sizes, int n_in,
                              void* d_out, int out_size) {
    const float* X      = (const float*)d_in[0];
    const float* mus    = (const float*)d_in[1];
    const float* sigmas = (const float*)d_in[2];
    const float* phis   = (const float*)d_in[3];
    float* out = (float*)d_out;

    int N = in_sizes[0] / DDIM;

    gmm_precompute<<<KMIX, 32>>>(sigmas, mus, phis);

    size_t shmem = (size_t)SM_SCR2 * sizeof(float)
                 + (size_t)KMIX * BLK * sizeof(unsigned long long)   // scr2
                 + (size_t)KMIX * BLK * sizeof(float);               // scr1
    cudaFuncSetAttribute((const void*)gmm_main,
                         cudaFuncAttributeMaxDynamicSharedMemorySize, (int)shmem);
    int blocks = (N + BLK * SPT - 1) / (BLK * SPT);
    gmm_main<<<blocks, BLK, shmem>>>(X, out, N);
}

// round 14
// speedup vs baseline: 2.1229x; 2.1229x over previous
#include <cuda_runtime.h>
#include <math.h>
#include <stdint.h>

#define KMIX 32
#define DDIM 32
#define TILE 256
#define NTH  256
#define XSTR 36   // padded row stride (floats): 16B-aligned, conflict-free A-frag loads

// ---- smem float offsets ----
#define OFF_B   0                       // 32768 f : B fragments (16384 float2, 128KB)
#define OFF_X   32768                   // 9216 f : X tile [256 x XSTR]
#define OFF_NLL (OFF_X + TILE * XSTR)   // 9216 f : nll [256 x XSTR]
#define OFF_NTP (OFF_NLL + TILE * XSTR) // 1024 f : -t pairs (512 float2)
#define OFF_C   (OFF_NTP + 1024)        // 32 f
#define SMEM_FLOATS (OFF_C + 32)

// ---- device-global precomputed data (no allocation) ----
__device__ float2 g_bfrag[KMIX * 4 * 4 * 32]; // [k][cb][kc][lane] = {M[cb*8+gid][kc*8+tig], M[..][..+4]}
__device__ float2 g_ntp[KMIX * 16];           // [k][c2] = {-t[2c2], -t[2c2+1]}
__device__ float  g_c[KMIX];

// ---------------- helpers ----------------
static __device__ __forceinline__ float tf32r(float x) {
    uint32_t r; asm("cvt.rna.tf32.f32 %0, %1;" : "=r"(r) : "f"(x));
    return __uint_as_float(r);
}
static __device__ __forceinline__ unsigned long long fma2(unsigned long long a,
                                                          unsigned long long b,
                                                          unsigned long long c) {
    unsigned long long d;
    asm("fma.rn.f32x2 %0, %1, %2, %3;" : "=l"(d) : "l"(a), "l"(b), "l"(c));
    return d;
}
static __device__ __forceinline__ unsigned long long add2(unsigned long long a,
                                                          unsigned long long b) {
    unsigned long long d;
    asm("add.rn.f32x2 %0, %1, %2;" : "=l"(d) : "l"(a), "l"(b));
    return d;
}
static __device__ __forceinline__ float hadd2(unsigned long long a) {
    float lo, hi;
    asm("mov.b64 {%0, %1}, %2;" : "=f"(lo), "=f"(hi) : "l"(a));
    return lo + hi;
}
static __device__ __forceinline__ unsigned long long pack2f(float lo, float hi) {
    unsigned long long d;
    asm("mov.b64 %0, {%1, %2};" : "=l"(d) : "f"(lo), "f"(hi));
    return d;
}

#define MMA_TF32(c0, c1, c2, c3, a0, a1, a2, a3, b0, b1)                         \
    asm volatile("mma.sync.aligned.m16n8k8.row.col.f32.tf32.tf32.f32 "           \
                 "{%0,%1,%2,%3}, {%4,%5,%6,%7}, {%8,%9}, {%0,%1,%2,%3};"         \
                 : "+f"(c0), "+f"(c1), "+f"(c2), "+f"(c3)                        \
                 : "r"(a0), "r"(a1), "r"(a2), "r"(a3), "r"(b0), "r"(b1))

// ---------------- precompute: one warp per mixture ----------------
__global__ void gmm_pre(const float* __restrict__ sigmas,
                        const float* __restrict__ mus,
                        const float* __restrict__ phis) {
    __shared__ float sL[1024];
    __shared__ float sMi[1024];
    __shared__ float sT[32];
    int k = blockIdx.x;
    int lane = threadIdx.x;
    int gid = lane >> 2, tig = lane & 3;

    for (int idx = lane; idx < 1024; idx += 32) {
        sL[idx] = sigmas[k * 1024 + idx];
        sMi[idx] = 0.0f;
    }
    __syncwarp();

    // Cholesky (lower)
    for (int j = 0; j < DDIM; j++) {
        float s = 0.0f;
        if (lane >= j) {
            s = sL[lane * 32 + j];
            for (int p = 0; p < j; p++) s -= sL[lane * 32 + p] * sL[j * 32 + p];
        }
        __syncwarp();
        if (lane == j) sL[j * 32 + j] = sqrtf(s);
        __syncwarp();
        if (lane > j) sL[lane * 32 + j] = s / sL[j * 32 + j];
        __syncwarp();
    }
    // Mi = L^-1 (lane c solves column c)
    {
        int c = lane;
        for (int i = c; i < DDIM; i++) {
            float s = (i == c) ? 1.0f : 0.0f;
            for (int p = c; p < i; p++) s -= sL[i * 32 + p] * sMi[p * 32 + c];
            sMi[i * 32 + c] = s / sL[i * 32 + i];
        }
    }
    __syncwarp();
    // tf32-round Mi in place (MMA operand == what t uses)
    for (int idx = lane; idx < 1024; idx += 32) {
        int i = idx >> 5, j = idx & 31;
        sMi[idx] = (j <= i) ? tf32r(sMi[idx]) : 0.0f;
    }
    __syncwarp();

    // B fragments in mma.sync register order
#pragma unroll
    for (int cb = 0; cb < 4; cb++)
#pragma unroll
        for (int kc = 0; kc < 4; kc++)
            g_bfrag[((k * 4 + cb) * 4 + kc) * 32 + lane] =
                make_float2(sMi[(cb * 8 + gid) * 32 + kc * 8 + tig],
                            sMi[(cb * 8 + gid) * 32 + kc * 8 + tig + 4]);

    // t_k = Mi * mu_k
    {
        float tv = 0.0f;
        for (int j = 0; j <= lane; j++) tv = fmaf(sMi[lane * 32 + j], mus[k * 32 + j], tv);
        sT[lane] = tv;
    }
    __syncwarp();
    if (lane < 16)
        g_ntp[k * 16 + lane] = make_float2(-sT[2 * lane], -sT[2 * lane + 1]);

    if (lane == 0) {
        float logdet = 0.0f;
        for (int j = 0; j < DDIM; j++) logdet += logf(sL[j * 32 + j]);
        logdet *= 2.0f;
        const float log2pi = 1.8378770664093453f;
        g_c[k] = -logf(phis[k]) + 0.5f * ((float)DDIM * log2pi + logdet);
    }
}

// ---------------- main: persistent tensor-core kernel ----------------
__global__ void __launch_bounds__(NTH, 1)
gmm_tc(const float* __restrict__ X, float* __restrict__ out, int N, int tiles) {
    extern __shared__ float sh[];
    const int tid = threadIdx.x;
    const int wid = tid >> 5;
    const int lane = tid & 31;
    const int gid = lane >> 2, tig = lane & 3;

    // stage constants once
    {
        const float4* src = reinterpret_cast<const float4*>(g_bfrag);
        float4* dst = reinterpret_cast<float4*>(sh + OFF_B);
        for (int i = tid; i < (KMIX * 4 * 4 * 32) / 2; i += NTH) dst[i] = src[i];
        const float4* s2 = reinterpret_cast<const float4*>(g_ntp);
        float4* d2 = reinterpret_cast<float4*>(sh + OFF_NTP);
        for (int i = tid; i < (KMIX * 16) / 2; i += NTH) d2[i] = s2[i];
        if (tid < KMIX) sh[OFF_C + tid] = g_c[tid];
    }
    __syncthreads();

    const unsigned long long* sB   = reinterpret_cast<const unsigned long long*>(sh + OFF_B);
    const unsigned long long* sNtp = reinterpret_cast<const unsigned long long*>(sh + OFF_NTP);

    for (int tile = blockIdx.x; tile < tiles; tile += gridDim.x) {
        // stage X tile (tf32-rounded), one row per thread
        {
            int n = tile * TILE + tid;
            if (n >= N) n = N - 1;
            const float4* xr = reinterpret_cast<const float4*>(X + (size_t)n * DDIM);
            float* xd = sh + OFF_X + tid * XSTR;
#pragma unroll
            for (int j = 0; j < 8; j++) {
                float4 v = xr[j];
                v.x = tf32r(v.x); v.y = tf32r(v.y); v.z = tf32r(v.z); v.w = tf32r(v.w);
                *reinterpret_cast<float4*>(xd + 4 * j) = v;
            }
        }
        __syncthreads();

        // A fragments: warp owns rows [wid*32, wid*32+32), two m16 row-blocks
        uint32_t a[2][4][4];
        {
            const float* xs = sh + OFF_X;
#pragma unroll
            for (int rb = 0; rb < 2; rb++) {
                int rowbase = wid * 32 + rb * 16;
#pragma unroll
                for (int kc = 0; kc < 4; kc++) {
                    a[rb][kc][0] = __float_as_uint(xs[(rowbase + gid) * XSTR + kc * 8 + tig]);
                    a[rb][kc][1] = __float_as_uint(xs[(rowbase + gid + 8) * XSTR + kc * 8 + tig]);
                    a[rb][kc][2] = __float_as_uint(xs[(rowbase + gid) * XSTR + kc * 8 + tig + 4]);
                    a[rb][kc][3] = __float_as_uint(xs[(rowbase + gid + 8) * XSTR + kc * 8 + tig + 4]);
                }
            }
        }

#pragma unroll 1
        for (int k = 0; k < KMIX; k++) {
            const unsigned long long* bk = sB + k * 512;
            unsigned long long q00 = 0ull, q01 = 0ull, q10 = 0ull, q11 = 0ull;
#pragma unroll
            for (int cb = 0; cb < 4; cb++) {
                float c0[4] = {0.f, 0.f, 0.f, 0.f};
                float c1[4] = {0.f, 0.f, 0.f, 0.f};
#pragma unroll
                for (int kc = 0; kc < 4; kc++) {
                    unsigned long long b = bk[(cb * 4 + kc) * 32 + lane];
                    uint32_t b0 = (uint32_t)b, b1 = (uint32_t)(b >> 32);
                    MMA_TF32(c0[0], c0[1], c0[2], c0[3],
                             a[0][kc][0], a[0][kc][1], a[0][kc][2], a[0][kc][3], b0, b1);
                    MMA_TF32(c1[0], c1[1], c1[2], c1[3],
                             a[1][kc][0], a[1][kc][1], a[1][kc][2], a[1][kc][3], b0, b1);
                }
                unsigned long long nt = sNtp[k * 16 + cb * 4 + tig];
                unsigned long long y;
                y = add2(pack2f(c0[0], c0[1]), nt); q00 = fma2(y, y, q00);
                y = add2(pack2f(c0[2], c0[3]), nt); q01 = fma2(y, y, q01);
                y = add2(pack2f(c1[0], c1[1]), nt); q10 = fma2(y, y, q10);
                y = add2(pack2f(c1[2], c1[3]), nt); q11 = fma2(y, y, q11);
            }
            float ck = sh[OFF_C + k];
            float ql0 = hadd2(q00), qh0 = hadd2(q01);
            float ql1 = hadd2(q10), qh1 = hadd2(q11);
            ql0 += __shfl_xor_sync(0xffffffffu, ql0, 1);
            ql0 += __shfl_xor_sync(0xffffffffu, ql0, 2);
            qh0 += __shfl_xor_sync(0xffffffffu, qh0, 1);
            qh0 += __shfl_xor_sync(0xffffffffu, qh0, 2);
            ql1 += __shfl_xor_sync(0xffffffffu, ql1, 1);
            ql1 += __shfl_xor_sync(0xffffffffu, ql1, 2);
            qh1 += __shfl_xor_sync(0xffffffffu, qh1, 1);
            qh1 += __shfl_xor_sync(0xffffffffu, qh1, 2);
            if (tig == 0) {
                int rb0 = wid * 32;
                sh[OFF_NLL + (rb0 + gid) * XSTR + k]      = fmaf(0.5f, ql0, ck);
                sh[OFF_NLL + (rb0 + gid + 8) * XSTR + k]  = fmaf(0.5f, qh0, ck);
                sh[OFF_NLL + (rb0 + 16 + gid) * XSTR + k]     = fmaf(0.5f, ql1, ck);
                sh[OFF_NLL + (rb0 + 16 + gid + 8) * XSTR + k] = fmaf(0.5f, qh1, ck);
            }
        }
        __syncthreads();

        // output: one row per thread, row-max normalize
        {
            int n = tile * TILE + tid;
            if (n < N) {
                const float* row = sh + OFF_NLL + tid * XSTR;
                float v[32];
                float mx = -3.0e38f;
#pragma unroll
                for (int j = 0; j < 32; j++) { v[j] = row[j]; mx = fmaxf(mx, v[j]); }
                float inv = 1.0f / mx;
                float4* op = reinterpret_cast<float4*>(out + (size_t)n * DDIM);
#pragma unroll
                for (int j = 0; j < 8; j++)
                    op[j] = make_float4(v[4 * j] * inv, v[4 * j + 1] * inv,
                                        v[4 * j + 2] * inv, v[4 * j + 3] * inv);
            }
        }
        __syncthreads();
    }
}

extern "C" void kernel_launch(void* const* d_in, const int* in_sizes, int n_in,
                              void* d_out, int out_size) {
    const float* X      = (const float*)d_in[0];
    const float* mus    = (const float*)d_in[1];
    const float* sigmas = (const float*)d_in[2];
    const float* phis   = (const float*)d_in[3];
    float* out = (float*)d_out;

    int N = in_sizes[0] / DDIM;
    int tiles = (N + TILE - 1) / TILE;

    static int smCount = 0;
    if (smCount == 0) {
        cudaDeviceGetAttribute(&smCount, cudaDevAttrMultiProcessorCount, 0);
        if (smCount <= 0) smCount = 148;
    }
    int grid = tiles < smCount ? tiles : smCount;

    gmm_pre<<<KMIX, 32>>>(sigmas, mus, phis);

    size_t shmem = (size_t)SMEM_FLOATS * sizeof(float);
    cudaFuncSetAttribute((const void*)gmm_tc,
                         cudaFuncAttributeMaxDynamicSharedMemorySize, (int)shmem);
    gmm_tc<<<grid, NTH, shmem>>>(X, out, N, tiles);
}